// round 4
// baseline (speedup 1.0000x reference)
#include <cuda_runtime.h>

#define C_IN  32
#define C_OUT 64
#define KNUM  8
#define TILE  1024
#define EPS   1e-5f

__device__ float g_sum[C_OUT];
__device__ float g_sumsq[C_OUT];
__device__ float g_a[C_OUT];
__device__ float g_b[C_OUT];

__device__ __forceinline__ unsigned long long pack2(float lo, float hi) {
    unsigned long long r;
    asm("mov.b64 %0, {%1, %2};" : "=l"(r) : "f"(lo), "f"(hi));
    return r;
}
__device__ __forceinline__ void unpack2(unsigned long long v, float& lo, float& hi) {
    asm("mov.b64 {%0, %1}, %2;" : "=f"(lo), "=f"(hi) : "l"(v));
}
#define FMA_F32X2(acc, a, b) \
    asm("fma.rn.f32x2 %0, %1, %2, %0;" : "+l"(acc) : "l"(a), "l"(b))

// ---------------------------------------------------------------------------
// Pass A: sparse conv + scatter. 8 warps/block; warp j owns kernel offset j,
// W[j] in registers as k-pair f32x2 operands (FFMA2 inner loop).
// x-broadcast via per-warp double-buffered smem staging + LDS.128 broadcast
// (replaces 32 SHFLs/voxel with 8 vector loads). Scatter = RED.64 per lane
// (proven round-2 path).
// ---------------------------------------------------------------------------
__global__ void __launch_bounds__(256, 2)
conv_scatter(const float* __restrict__ x,
             const float* __restrict__ W,
             const int*   __restrict__ kidx,
             const int*   __restrict__ oidx,
             float*       __restrict__ out,
             int n)
{
    __shared__ int    bins[KNUM][TILE];
    __shared__ int    cnts[KNUM];
    __shared__ float4 xbuf[KNUM][2][C_IN / 4];   // per-warp staging, 2 buffers

    const int tid  = threadIdx.x;
    const int lane = tid & 31;
    const int wid  = tid >> 5;          // warp id == kernel offset j

    if (blockIdx.x == 0 && tid < C_OUT) { g_sum[tid] = 0.f; g_sumsq[tid] = 0.f; }

    // W[wid] packed for this lane's channel pair (2l, 2l+1), k-paired:
    // wp0[p] = (W[2p][2l], W[2p+1][2l]), wp1[p] = same for channel 2l+1.
    unsigned long long wp0[C_IN / 2], wp1[C_IN / 2];
    {
        const float* Wj = W + wid * (C_IN * C_OUT);
        #pragma unroll
        for (int p = 0; p < C_IN / 2; ++p) {
            float2 ta = ((const float2*)(Wj + (2 * p)     * C_OUT))[lane];
            float2 tb = ((const float2*)(Wj + (2 * p + 1) * C_OUT))[lane];
            wp0[p] = pack2(ta.x, tb.x);
            wp1[p] = pack2(ta.y, tb.y);
        }
    }

    const int tileBase = blockIdx.x * TILE;

    if (tid < KNUM) cnts[tid] = 0;
    __syncthreads();

    #pragma unroll
    for (int u = 0; u < TILE / 256; ++u) {
        int i = tileBase + u * 256 + tid;
        if (i < n) {
            int k   = kidx[i];
            int pos = atomicAdd(&cnts[k], 1);
            bins[k][pos] = i;
        }
    }
    __syncthreads();

    const int cnt = cnts[wid];
    if (cnt == 0) return;

    // Pipeline prologue: voxel 0 into buffer 0.
    {
        int i0 = bins[wid][0];
        ((float*)&xbuf[wid][0][0])[lane] = x[(size_t)i0 * C_IN + lane];
    }
    int o = oidx[bins[wid][0]];
    __syncwarp();

    for (int p = 0; p < cnt; ++p) {
        // Prefetch next voxel's x row (register) + out index.
        float xn = 0.f; int on = 0;
        if (p + 1 < cnt) {
            int i1 = bins[wid][p + 1];
            xn = x[(size_t)i1 * C_IN + lane];
            on = oidx[i1];
        }

        // Compute from staged buffer: 8 broadcast LDS.128, 32 FFMA2.
        const float4* xb = &xbuf[wid][p & 1][0];
        unsigned long long acc0 = 0ull, acc1 = 0ull;
        #pragma unroll
        for (int t = 0; t < C_IN / 4; ++t) {
            float4 v = xb[t];                         // broadcast (N=1)
            unsigned long long v01 = pack2(v.x, v.y); // k = 4t, 4t+1
            unsigned long long v23 = pack2(v.z, v.w); // k = 4t+2, 4t+3
            FMA_F32X2(acc0, v01, wp0[2 * t]);
            FMA_F32X2(acc1, v01, wp1[2 * t]);
            FMA_F32X2(acc0, v23, wp0[2 * t + 1]);
            FMA_F32X2(acc1, v23, wp1[2 * t + 1]);
        }
        float a0l, a0h, a1l, a1h;
        unpack2(acc0, a0l, a0h);
        unpack2(acc1, a1l, a1h);
        float a0 = a0l + a0h;       // channel 2*lane
        float a1 = a1l + a1h;       // channel 2*lane + 1

        float2* dst = (float2*)(out + (size_t)o * C_OUT) + lane;
        atomicAdd(dst, make_float2(a0, a1));          // RED.64

        // Stage next voxel into the other buffer.
        ((float*)&xbuf[wid][(p + 1) & 1][0])[lane] = xn;
        __syncwarp();
        o = on;
    }
}

// ---------------------------------------------------------------------------
// Pass B: per-channel sum / sum-of-squares, float4 + unroll-2 for MLP.
// ---------------------------------------------------------------------------
__global__ void stats_pass(const float4* __restrict__ out4, int n4)
{
    float4 s  = make_float4(0.f, 0.f, 0.f, 0.f);
    float4 s2 = make_float4(0.f, 0.f, 0.f, 0.f);
    const int start  = blockIdx.x * blockDim.x + threadIdx.x;
    const int stride = blockDim.x * gridDim.x;   // multiple of 16
    for (int i = start; i < n4; i += 2 * stride) {
        float4 v0 = out4[i];
        int j = i + stride;
        float4 v1 = (j < n4) ? out4[j] : make_float4(0.f, 0.f, 0.f, 0.f);
        s.x += v0.x + v1.x; s.y += v0.y + v1.y;
        s.z += v0.z + v1.z; s.w += v0.w + v1.w;
        s2.x = fmaf(v0.x, v0.x, fmaf(v1.x, v1.x, s2.x));
        s2.y = fmaf(v0.y, v0.y, fmaf(v1.y, v1.y, s2.y));
        s2.z = fmaf(v0.z, v0.z, fmaf(v1.z, v1.z, s2.z));
        s2.w = fmaf(v0.w, v0.w, fmaf(v1.w, v1.w, s2.w));
    }

    __shared__ float sh1[C_OUT], sh2[C_OUT];
    if (threadIdx.x < C_OUT) { sh1[threadIdx.x] = 0.f; sh2[threadIdx.x] = 0.f; }
    __syncthreads();
    const int cg = (start & 15) * 4;             // fixed channel group base
    atomicAdd(&sh1[cg + 0], s.x);  atomicAdd(&sh1[cg + 1], s.y);
    atomicAdd(&sh1[cg + 2], s.z);  atomicAdd(&sh1[cg + 3], s.w);
    atomicAdd(&sh2[cg + 0], s2.x); atomicAdd(&sh2[cg + 1], s2.y);
    atomicAdd(&sh2[cg + 2], s2.z); atomicAdd(&sh2[cg + 3], s2.w);
    __syncthreads();
    if (threadIdx.x < C_OUT) {
        atomicAdd(&g_sum[threadIdx.x],   sh1[threadIdx.x]);
        atomicAdd(&g_sumsq[threadIdx.x], sh2[threadIdx.x]);
    }
}

// ---------------------------------------------------------------------------
// Pass C: finalize BN affine (conv bias cancels algebraically).
// ---------------------------------------------------------------------------
__global__ void finalize_stats(const float* __restrict__ gamma,
                               const float* __restrict__ beta,
                               float inv_n)
{
    const int c = threadIdx.x;
    float mean = g_sum[c] * inv_n;
    float var  = g_sumsq[c] * inv_n - mean * mean;
    float a    = gamma[c] * rsqrtf(var + EPS);
    g_a[c] = a;
    g_b[c] = fmaf(-mean, a, beta[c]);
}

// ---------------------------------------------------------------------------
// Pass D: in-place normalize + ReLU, float4 + unroll-2.
// ---------------------------------------------------------------------------
__global__ void norm_relu(float4* __restrict__ out4, int n4)
{
    const int start  = blockIdx.x * blockDim.x + threadIdx.x;
    const int stride = blockDim.x * gridDim.x;   // multiple of 16
    const int cg = (start & 15) * 4;
    const float4 a = *(const float4*)&g_a[cg];
    const float4 b = *(const float4*)&g_b[cg];
    for (int i = start; i < n4; i += 2 * stride) {
        float4 v0 = out4[i];
        int j = i + stride;
        bool has1 = (j < n4);
        float4 v1 = has1 ? out4[j] : make_float4(0.f, 0.f, 0.f, 0.f);
        v0.x = fmaxf(fmaf(v0.x, a.x, b.x), 0.f);
        v0.y = fmaxf(fmaf(v0.y, a.y, b.y), 0.f);
        v0.z = fmaxf(fmaf(v0.z, a.z, b.z), 0.f);
        v0.w = fmaxf(fmaf(v0.w, a.w, b.w), 0.f);
        out4[i] = v0;
        if (has1) {
            v1.x = fmaxf(fmaf(v1.x, a.x, b.x), 0.f);
            v1.y = fmaxf(fmaf(v1.y, a.y, b.y), 0.f);
            v1.z = fmaxf(fmaf(v1.z, a.z, b.z), 0.f);
            v1.w = fmaxf(fmaf(v1.w, a.w, b.w), 0.f);
            out4[j] = v1;
        }
    }
}

// ---------------------------------------------------------------------------
// Launch. Inputs: x, W, bias, gamma, beta, k_idx, out_idx, num_out.
// ---------------------------------------------------------------------------
extern "C" void kernel_launch(void* const* d_in, const int* in_sizes, int n_in,
                              void* d_out, int out_size)
{
    const float* x     = (const float*)d_in[0];
    const float* W     = (const float*)d_in[1];
    const float* gamma = (const float*)d_in[3];
    const float* beta  = (const float*)d_in[4];
    const int*   kidx  = (const int*)d_in[5];
    const int*   oidx  = (const int*)d_in[6];

    const int n       = in_sizes[0] / C_IN;
    const int total   = out_size;               // num_out * 64
    const int num_out = total / C_OUT;
    const int n4      = total / 4;

    cudaMemsetAsync(d_out, 0, (size_t)total * sizeof(float), 0);

    const int tiles = (n + TILE - 1) / TILE;
    conv_scatter<<<tiles, 256>>>(x, W, kidx, oidx, (float*)d_out, n);
    stats_pass<<<1184, 256>>>((const float4*)d_out, n4);
    finalize_stats<<<1, C_OUT>>>(gamma, beta, 1.0f / (float)num_out);
    norm_relu<<<1184, 256>>>((float4*)d_out, n4);
}

// round 5
// speedup vs baseline: 1.0036x; 1.0036x over previous
#include <cuda_runtime.h>

#define C_IN  32
#define C_OUT 64
#define KNUM  8
#define TILE  1024
#define EPS   1e-5f
#define MAX_OUT (8 * 64 * 64 * 64)   // B * (GRID/2)^3 upper bound

__device__ float g_sum[C_OUT];
__device__ float g_sumsq[C_OUT];
__device__ float g_a[C_OUT];
__device__ float g_b[C_OUT];
__device__ int   g_cnt[MAX_OUT];     // contributors per output row

__device__ __forceinline__ unsigned long long pack2(float lo, float hi) {
    unsigned long long r;
    asm("mov.b64 %0, {%1, %2};" : "=l"(r) : "f"(lo), "f"(hi));
    return r;
}
__device__ __forceinline__ void unpack2(unsigned long long v, float& lo, float& hi) {
    asm("mov.b64 {%0, %1}, %2;" : "=f"(lo), "=f"(hi) : "l"(v));
}
#define FMA_F32X2(acc, a, b) \
    asm("fma.rn.f32x2 %0, %1, %2, %0;" : "+l"(acc) : "l"(a), "l"(b))

// ---------------------------------------------------------------------------
// Pass 0a: zero per-row contributor counters + stat accumulators.
// ---------------------------------------------------------------------------
__global__ void zero_counts(int num_out)
{
    const int start  = blockIdx.x * blockDim.x + threadIdx.x;
    const int stride = blockDim.x * gridDim.x;
    for (int i = start; i < num_out; i += stride) g_cnt[i] = 0;
    if (start < C_OUT) { g_sum[start] = 0.f; g_sumsq[start] = 0.f; }
}

// ---------------------------------------------------------------------------
// Pass 0b: count contributors per output row (int REDs, cheap).
// ---------------------------------------------------------------------------
__global__ void count_rows(const int* __restrict__ oidx, int n)
{
    const int start  = blockIdx.x * blockDim.x + threadIdx.x;
    const int stride = blockDim.x * gridDim.x;
    for (int i = start; i < n; i += stride) atomicAdd(&g_cnt[oidx[i]], 1);
}

// ---------------------------------------------------------------------------
// Pass A: sparse conv + scatter (round-2 proven compute body).
// 8 warps/block; warp j owns kernel offset j with W[j] in registers as
// k-pair f32x2 operands; x broadcast via SHFL; FFMA2 inner loop.
// Scatter: rows with a single contributor use plain STG.64 (no atomic);
// multi-contributor rows use RED.64.
// ---------------------------------------------------------------------------
__global__ void __launch_bounds__(256, 2)
conv_scatter(const float* __restrict__ x,
             const float* __restrict__ W,
             const int*   __restrict__ kidx,
             const int*   __restrict__ oidx,
             float*       __restrict__ out,
             int n)
{
    __shared__ int bins[KNUM][TILE];
    __shared__ int cnts[KNUM];

    const int tid  = threadIdx.x;
    const int lane = tid & 31;
    const int wid  = tid >> 5;          // warp id == kernel offset j

    // W[wid] packed for this lane's channel pair (2l, 2l+1), k-paired.
    unsigned long long wp0[C_IN / 2], wp1[C_IN / 2];
    {
        const float* Wj = W + wid * (C_IN * C_OUT);
        #pragma unroll
        for (int p = 0; p < C_IN / 2; ++p) {
            float2 ta = ((const float2*)(Wj + (2 * p)     * C_OUT))[lane];
            float2 tb = ((const float2*)(Wj + (2 * p + 1) * C_OUT))[lane];
            wp0[p] = pack2(ta.x, tb.x);
            wp1[p] = pack2(ta.y, tb.y);
        }
    }

    const int tileBase = blockIdx.x * TILE;

    if (tid < KNUM) cnts[tid] = 0;
    __syncthreads();

    #pragma unroll
    for (int u = 0; u < TILE / 256; ++u) {
        int i = tileBase + u * 256 + tid;
        if (i < n) {
            int k   = kidx[i];
            int pos = atomicAdd(&cnts[k], 1);
            bins[k][pos] = i;
        }
    }
    __syncthreads();

    const int cnt = cnts[wid];
    if (cnt == 0) return;

    // Software pipeline prologue.
    int   i0 = bins[wid][0];
    float xv = x[(size_t)i0 * C_IN + lane];
    int   o  = oidx[i0];
    int   c  = g_cnt[o];

    for (int p = 0; p < cnt; ++p) {
        // Prefetch next voxel's x-row, out index, contributor count.
        float xv_n = 0.f; int o_n = 0, c_n = 0;
        if (p + 1 < cnt) {
            int i1 = bins[wid][p + 1];
            xv_n = x[(size_t)i1 * C_IN + lane];
            o_n  = oidx[i1];
            c_n  = g_cnt[o_n];
        }

        unsigned long long acc0 = 0ull, acc1 = 0ull;
        #pragma unroll
        for (int q = 0; q < C_IN / 2; ++q) {
            float va = __shfl_sync(0xffffffffu, xv, 2 * q);
            float vb = __shfl_sync(0xffffffffu, xv, 2 * q + 1);
            unsigned long long vv = pack2(va, vb);
            FMA_F32X2(acc0, vv, wp0[q]);
            FMA_F32X2(acc1, vv, wp1[q]);
        }
        float a0l, a0h, a1l, a1h;
        unpack2(acc0, a0l, a0h);
        unpack2(acc1, a1l, a1h);
        float a0 = a0l + a0h;       // channel 2*lane
        float a1 = a1l + a1h;       // channel 2*lane + 1

        float2* dst = (float2*)(out + (size_t)o * C_OUT) + lane;
        if (c == 1) {
            *dst = make_float2(a0, a1);            // sole contributor: STG.64
        } else {
            atomicAdd(dst, make_float2(a0, a1));   // RED.64
        }

        xv = xv_n; o = o_n; c = c_n;
    }
}

// ---------------------------------------------------------------------------
// Pass B: per-channel sum / sum-of-squares, float4 + unroll-2 for MLP.
// ---------------------------------------------------------------------------
__global__ void stats_pass(const float4* __restrict__ out4, int n4)
{
    float4 s  = make_float4(0.f, 0.f, 0.f, 0.f);
    float4 s2 = make_float4(0.f, 0.f, 0.f, 0.f);
    const int start  = blockIdx.x * blockDim.x + threadIdx.x;
    const int stride = blockDim.x * gridDim.x;   // multiple of 16
    for (int i = start; i < n4; i += 2 * stride) {
        float4 v0 = out4[i];
        int j = i + stride;
        float4 v1 = (j < n4) ? out4[j] : make_float4(0.f, 0.f, 0.f, 0.f);
        s.x += v0.x + v1.x; s.y += v0.y + v1.y;
        s.z += v0.z + v1.z; s.w += v0.w + v1.w;
        s2.x = fmaf(v0.x, v0.x, fmaf(v1.x, v1.x, s2.x));
        s2.y = fmaf(v0.y, v0.y, fmaf(v1.y, v1.y, s2.y));
        s2.z = fmaf(v0.z, v0.z, fmaf(v1.z, v1.z, s2.z));
        s2.w = fmaf(v0.w, v0.w, fmaf(v1.w, v1.w, s2.w));
    }

    __shared__ float sh1[C_OUT], sh2[C_OUT];
    if (threadIdx.x < C_OUT) { sh1[threadIdx.x] = 0.f; sh2[threadIdx.x] = 0.f; }
    __syncthreads();
    const int cg = (start & 15) * 4;             // fixed channel group base
    atomicAdd(&sh1[cg + 0], s.x);  atomicAdd(&sh1[cg + 1], s.y);
    atomicAdd(&sh1[cg + 2], s.z);  atomicAdd(&sh1[cg + 3], s.w);
    atomicAdd(&sh2[cg + 0], s2.x); atomicAdd(&sh2[cg + 1], s2.y);
    atomicAdd(&sh2[cg + 2], s2.z); atomicAdd(&sh2[cg + 3], s2.w);
    __syncthreads();
    if (threadIdx.x < C_OUT) {
        atomicAdd(&g_sum[threadIdx.x],   sh1[threadIdx.x]);
        atomicAdd(&g_sumsq[threadIdx.x], sh2[threadIdx.x]);
    }
}

// ---------------------------------------------------------------------------
// Pass C: finalize BN affine (conv bias cancels algebraically).
// ---------------------------------------------------------------------------
__global__ void finalize_stats(const float* __restrict__ gamma,
                               const float* __restrict__ beta,
                               float inv_n)
{
    const int c = threadIdx.x;
    float mean = g_sum[c] * inv_n;
    float var  = g_sumsq[c] * inv_n - mean * mean;
    float a    = gamma[c] * rsqrtf(var + EPS);
    g_a[c] = a;
    g_b[c] = fmaf(-mean, a, beta[c]);
}

// ---------------------------------------------------------------------------
// Pass D: in-place normalize + ReLU, float4 + unroll-2.
// ---------------------------------------------------------------------------
__global__ void norm_relu(float4* __restrict__ out4, int n4)
{
    const int start  = blockIdx.x * blockDim.x + threadIdx.x;
    const int stride = blockDim.x * gridDim.x;   // multiple of 16
    const int cg = (start & 15) * 4;
    const float4 a = *(const float4*)&g_a[cg];
    const float4 b = *(const float4*)&g_b[cg];
    for (int i = start; i < n4; i += 2 * stride) {
        float4 v0 = out4[i];
        int j = i + stride;
        bool has1 = (j < n4);
        float4 v1 = has1 ? out4[j] : make_float4(0.f, 0.f, 0.f, 0.f);
        v0.x = fmaxf(fmaf(v0.x, a.x, b.x), 0.f);
        v0.y = fmaxf(fmaf(v0.y, a.y, b.y), 0.f);
        v0.z = fmaxf(fmaf(v0.z, a.z, b.z), 0.f);
        v0.w = fmaxf(fmaf(v0.w, a.w, b.w), 0.f);
        out4[i] = v0;
        if (has1) {
            v1.x = fmaxf(fmaf(v1.x, a.x, b.x), 0.f);
            v1.y = fmaxf(fmaf(v1.y, a.y, b.y), 0.f);
            v1.z = fmaxf(fmaf(v1.z, a.z, b.z), 0.f);
            v1.w = fmaxf(fmaf(v1.w, a.w, b.w), 0.f);
            out4[j] = v1;
        }
    }
}

// ---------------------------------------------------------------------------
// Launch. Inputs: x, W, bias, gamma, beta, k_idx, out_idx, num_out.
// ---------------------------------------------------------------------------
extern "C" void kernel_launch(void* const* d_in, const int* in_sizes, int n_in,
                              void* d_out, int out_size)
{
    const float* x     = (const float*)d_in[0];
    const float* W     = (const float*)d_in[1];
    const float* gamma = (const float*)d_in[3];
    const float* beta  = (const float*)d_in[4];
    const int*   kidx  = (const int*)d_in[5];
    const int*   oidx  = (const int*)d_in[6];

    const int n       = in_sizes[0] / C_IN;
    const int total   = out_size;               // num_out * 64
    const int num_out = total / C_OUT;
    const int n4      = total / 4;

    cudaMemsetAsync(d_out, 0, (size_t)total * sizeof(float), 0);
    zero_counts<<<592, 256>>>(num_out);
    count_rows<<<592, 256>>>(oidx, n);

    const int tiles = (n + TILE - 1) / TILE;
    conv_scatter<<<tiles, 256>>>(x, W, kidx, oidx, (float*)d_out, n);
    stats_pass<<<1184, 256>>>((const float4*)d_out, n4);
    finalize_stats<<<1, C_OUT>>>(gamma, beta, 1.0f / (float)num_out);
    norm_relu<<<1184, 256>>>((float4*)d_out, n4);
}

// round 6
// speedup vs baseline: 1.4366x; 1.4315x over previous
#include <cuda_runtime.h>

#define C_IN  32
#define C_OUT 64
#define KNUM  8
#define TILE  1024
#define EPS   1e-5f

__device__ float g_sum[C_OUT];
__device__ float g_sumsq[C_OUT];
__device__ float g_a[C_OUT];
__device__ float g_b[C_OUT];

__device__ __forceinline__ unsigned long long pack2(float lo, float hi) {
    unsigned long long r;
    asm("mov.b64 %0, {%1, %2};" : "=l"(r) : "f"(lo), "f"(hi));
    return r;
}
__device__ __forceinline__ void unpack2(unsigned long long v, float& lo, float& hi) {
    asm("mov.b64 {%0, %1}, %2;" : "=f"(lo), "=f"(hi) : "l"(v));
}
#define FMA_F32X2(acc, a, b) \
    asm("fma.rn.f32x2 %0, %1, %2, %0;" : "+l"(acc) : "l"(a), "l"(b))

// ---------------------------------------------------------------------------
// Pass A: sparse conv + scatter. 8 warps/block; warp j owns kernel offset j,
// W[j] in registers as k-pair f32x2 operands; x broadcast via SHFL; FFMA2
// inner loop; RED.64 scatter (round-2 proven body).
// NEW: depth-4 software pipeline with front-batched LDGs per 4-voxel chunk
// (MLP=4 per warp) to cover the ~577-cycle DRAM latency of gathered x-rows.
// ---------------------------------------------------------------------------
__global__ void __launch_bounds__(256, 2)
conv_scatter(const float* __restrict__ x,
             const float* __restrict__ W,
             const int*   __restrict__ kidx,
             const int*   __restrict__ oidx,
             float*       __restrict__ out,
             int n)
{
    __shared__ int bins[KNUM][TILE];
    __shared__ int cnts[KNUM];

    const int tid  = threadIdx.x;
    const int lane = tid & 31;
    const int wid  = tid >> 5;          // warp id == kernel offset j

    if (blockIdx.x == 0 && tid < C_OUT) { g_sum[tid] = 0.f; g_sumsq[tid] = 0.f; }

    // W[wid] packed for this lane's channel pair (2l, 2l+1), k-paired:
    // wp0[p] = (W[2p][2l], W[2p+1][2l]), wp1[p] = same for channel 2l+1.
    unsigned long long wp0[C_IN / 2], wp1[C_IN / 2];
    {
        const float* Wj = W + wid * (C_IN * C_OUT);
        #pragma unroll
        for (int p = 0; p < C_IN / 2; ++p) {
            float2 ta = ((const float2*)(Wj + (2 * p)     * C_OUT))[lane];
            float2 tb = ((const float2*)(Wj + (2 * p + 1) * C_OUT))[lane];
            wp0[p] = pack2(ta.x, tb.x);
            wp1[p] = pack2(ta.y, tb.y);
        }
    }

    const int tileBase = blockIdx.x * TILE;

    if (tid < KNUM) cnts[tid] = 0;
    __syncthreads();

    #pragma unroll
    for (int u = 0; u < TILE / 256; ++u) {
        int i = tileBase + u * 256 + tid;
        if (i < n) {
            int k   = kidx[i];
            int pos = atomicAdd(&cnts[k], 1);
            bins[k][pos] = i;
        }
    }
    __syncthreads();

    const int cnt = cnts[wid];
    if (cnt == 0) return;

    // ---- Depth-4 pipeline. Slots hold voxels [base .. base+3]. ----
    float xq[4]; int oq[4];
    #pragma unroll
    for (int d = 0; d < 4; ++d) {
        if (d < cnt) {
            int i = bins[wid][d];
            xq[d] = x[(size_t)i * C_IN + lane];
            oq[d] = oidx[i];
        } else { xq[d] = 0.f; oq[d] = 0; }
    }

    for (int base = 0; base < cnt; base += 4) {
        // Front-batched prefetch of the NEXT chunk (4 independent LDGs).
        float xn[4]; int on[4];
        #pragma unroll
        for (int d = 0; d < 4; ++d) {
            int pf = base + 4 + d;
            if (pf < cnt) {
                int i = bins[wid][pf];
                xn[d] = x[(size_t)i * C_IN + lane];
                on[d] = oidx[i];
            } else { xn[d] = 0.f; on[d] = 0; }
        }

        // Compute the current chunk from registers.
        #pragma unroll
        for (int d = 0; d < 4; ++d) {
            if (base + d < cnt) {
                float xv = xq[d];
                unsigned long long acc0 = 0ull, acc1 = 0ull;
                #pragma unroll
                for (int q = 0; q < C_IN / 2; ++q) {
                    float va = __shfl_sync(0xffffffffu, xv, 2 * q);
                    float vb = __shfl_sync(0xffffffffu, xv, 2 * q + 1);
                    unsigned long long vv = pack2(va, vb);
                    FMA_F32X2(acc0, vv, wp0[q]);
                    FMA_F32X2(acc1, vv, wp1[q]);
                }
                float a0l, a0h, a1l, a1h;
                unpack2(acc0, a0l, a0h);
                unpack2(acc1, a1l, a1h);
                float a0 = a0l + a0h;       // channel 2*lane
                float a1 = a1l + a1h;       // channel 2*lane + 1

                float2* dst = (float2*)(out + (size_t)oq[d] * C_OUT) + lane;
                atomicAdd(dst, make_float2(a0, a1));   // RED.64
            }
        }

        // Rotate prefetched chunk into the active slots.
        #pragma unroll
        for (int d = 0; d < 4; ++d) { xq[d] = xn[d]; oq[d] = on[d]; }
    }
}

// ---------------------------------------------------------------------------
// Pass B: per-channel sum / sum-of-squares, float4 + unroll-2 for MLP.
// ---------------------------------------------------------------------------
__global__ void stats_pass(const float4* __restrict__ out4, int n4)
{
    float4 s  = make_float4(0.f, 0.f, 0.f, 0.f);
    float4 s2 = make_float4(0.f, 0.f, 0.f, 0.f);
    const int start  = blockIdx.x * blockDim.x + threadIdx.x;
    const int stride = blockDim.x * gridDim.x;   // multiple of 16
    for (int i = start; i < n4; i += 2 * stride) {
        float4 v0 = out4[i];
        int j = i + stride;
        float4 v1 = (j < n4) ? out4[j] : make_float4(0.f, 0.f, 0.f, 0.f);
        s.x += v0.x + v1.x; s.y += v0.y + v1.y;
        s.z += v0.z + v1.z; s.w += v0.w + v1.w;
        s2.x = fmaf(v0.x, v0.x, fmaf(v1.x, v1.x, s2.x));
        s2.y = fmaf(v0.y, v0.y, fmaf(v1.y, v1.y, s2.y));
        s2.z = fmaf(v0.z, v0.z, fmaf(v1.z, v1.z, s2.z));
        s2.w = fmaf(v0.w, v0.w, fmaf(v1.w, v1.w, s2.w));
    }

    __shared__ float sh1[C_OUT], sh2[C_OUT];
    if (threadIdx.x < C_OUT) { sh1[threadIdx.x] = 0.f; sh2[threadIdx.x] = 0.f; }
    __syncthreads();
    const int cg = (start & 15) * 4;             // fixed channel group base
    atomicAdd(&sh1[cg + 0], s.x);  atomicAdd(&sh1[cg + 1], s.y);
    atomicAdd(&sh1[cg + 2], s.z);  atomicAdd(&sh1[cg + 3], s.w);
    atomicAdd(&sh2[cg + 0], s2.x); atomicAdd(&sh2[cg + 1], s2.y);
    atomicAdd(&sh2[cg + 2], s2.z); atomicAdd(&sh2[cg + 3], s2.w);
    __syncthreads();
    if (threadIdx.x < C_OUT) {
        atomicAdd(&g_sum[threadIdx.x],   sh1[threadIdx.x]);
        atomicAdd(&g_sumsq[threadIdx.x], sh2[threadIdx.x]);
    }
}

// ---------------------------------------------------------------------------
// Pass C: finalize BN affine (conv bias cancels algebraically).
// ---------------------------------------------------------------------------
__global__ void finalize_stats(const float* __restrict__ gamma,
                               const float* __restrict__ beta,
                               float inv_n)
{
    const int c = threadIdx.x;
    float mean = g_sum[c] * inv_n;
    float var  = g_sumsq[c] * inv_n - mean * mean;
    float a    = gamma[c] * rsqrtf(var + EPS);
    g_a[c] = a;
    g_b[c] = fmaf(-mean, a, beta[c]);
}

// ---------------------------------------------------------------------------
// Pass D: in-place normalize + ReLU, float4 + unroll-2.
// ---------------------------------------------------------------------------
__global__ void norm_relu(float4* __restrict__ out4, int n4)
{
    const int start  = blockIdx.x * blockDim.x + threadIdx.x;
    const int stride = blockDim.x * gridDim.x;   // multiple of 16
    const int cg = (start & 15) * 4;
    const float4 a = *(const float4*)&g_a[cg];
    const float4 b = *(const float4*)&g_b[cg];
    for (int i = start; i < n4; i += 2 * stride) {
        float4 v0 = out4[i];
        int j = i + stride;
        bool has1 = (j < n4);
        float4 v1 = has1 ? out4[j] : make_float4(0.f, 0.f, 0.f, 0.f);
        v0.x = fmaxf(fmaf(v0.x, a.x, b.x), 0.f);
        v0.y = fmaxf(fmaf(v0.y, a.y, b.y), 0.f);
        v0.z = fmaxf(fmaf(v0.z, a.z, b.z), 0.f);
        v0.w = fmaxf(fmaf(v0.w, a.w, b.w), 0.f);
        out4[i] = v0;
        if (has1) {
            v1.x = fmaxf(fmaf(v1.x, a.x, b.x), 0.f);
            v1.y = fmaxf(fmaf(v1.y, a.y, b.y), 0.f);
            v1.z = fmaxf(fmaf(v1.z, a.z, b.z), 0.f);
            v1.w = fmaxf(fmaf(v1.w, a.w, b.w), 0.f);
            out4[j] = v1;
        }
    }
}

// ---------------------------------------------------------------------------
// Launch. Inputs: x, W, bias, gamma, beta, k_idx, out_idx, num_out.
// ---------------------------------------------------------------------------
extern "C" void kernel_launch(void* const* d_in, const int* in_sizes, int n_in,
                              void* d_out, int out_size)
{
    const float* x     = (const float*)d_in[0];
    const float* W     = (const float*)d_in[1];
    const float* gamma = (const float*)d_in[3];
    const float* beta  = (const float*)d_in[4];
    const int*   kidx  = (const int*)d_in[5];
    const int*   oidx  = (const int*)d_in[6];

    const int n       = in_sizes[0] / C_IN;
    const int total   = out_size;               // num_out * 64
    const int num_out = total / C_OUT;
    const int n4      = total / 4;

    cudaMemsetAsync(d_out, 0, (size_t)total * sizeof(float), 0);

    const int tiles = (n + TILE - 1) / TILE;
    conv_scatter<<<tiles, 256>>>(x, W, kidx, oidx, (float*)d_out, n);
    stats_pass<<<1184, 256>>>((const float4*)d_out, n4);
    finalize_stats<<<1, C_OUT>>>(gamma, beta, 1.0f / (float)num_out);
    norm_relu<<<1184, 256>>>((float4*)d_out, n4);
}

// round 7
// speedup vs baseline: 1.5961x; 1.1110x over previous
#include <cuda_runtime.h>

#define C_IN  32
#define C_OUT 64
#define KNUM  8
#define TILE  1024
#define EPS   1e-5f

__device__ float g_sum[C_OUT];
__device__ float g_sumsq[C_OUT];
__device__ float g_a[C_OUT];
__device__ float g_b[C_OUT];

__device__ __forceinline__ unsigned long long pack2(float lo, float hi) {
    unsigned long long r;
    asm("mov.b64 %0, {%1, %2};" : "=l"(r) : "f"(lo), "f"(hi));
    return r;
}
__device__ __forceinline__ void unpack2(unsigned long long v, float& lo, float& hi) {
    asm("mov.b64 {%0, %1}, %2;" : "=f"(lo), "=f"(hi) : "l"(v));
}
#define FMA_F32X2(acc, a, b) \
    asm("fma.rn.f32x2 %0, %1, %2, %0;" : "+l"(acc) : "l"(a), "l"(b))

// ---------------------------------------------------------------------------
// Pass A: sparse conv + scatter. 8 warps/block; warp j owns kernel offset j,
// W[j] in registers as k-pair f32x2 operands (FFMA2 inner loop); RED.64
// scatter (proven). x-rows staged GMEM->SMEM via cp.async in double-buffered
// 4-voxel chunks; compute reads them as broadcast LDS.128 (replaces 32
// SHFLs/voxel with 8 vector loads — MIO pressure ~3x lower), while cp.async
// keeps 4 row-fetches in flight to cover DRAM latency.
// ---------------------------------------------------------------------------
__global__ void __launch_bounds__(256, 2)
conv_scatter(const float* __restrict__ x,
             const float* __restrict__ W,
             const int*   __restrict__ kidx,
             const int*   __restrict__ oidx,
             float*       __restrict__ out,
             int n)
{
    __shared__ int    bins[KNUM][TILE];
    __shared__ int    cnts[KNUM];
    __shared__ float4 xstage[KNUM][2][4][C_IN / 4];  // [warp][buf][slot][row]

    const int tid  = threadIdx.x;
    const int lane = tid & 31;
    const int wid  = tid >> 5;          // warp id == kernel offset j

    if (blockIdx.x == 0 && tid < C_OUT) { g_sum[tid] = 0.f; g_sumsq[tid] = 0.f; }

    // W[wid] packed for this lane's channel pair (2l, 2l+1), k-paired.
    unsigned long long wp0[C_IN / 2], wp1[C_IN / 2];
    {
        const float* Wj = W + wid * (C_IN * C_OUT);
        #pragma unroll
        for (int p = 0; p < C_IN / 2; ++p) {
            float2 ta = ((const float2*)(Wj + (2 * p)     * C_OUT))[lane];
            float2 tb = ((const float2*)(Wj + (2 * p + 1) * C_OUT))[lane];
            wp0[p] = pack2(ta.x, tb.x);
            wp1[p] = pack2(ta.y, tb.y);
        }
    }

    const int tileBase = blockIdx.x * TILE;

    if (tid < KNUM) cnts[tid] = 0;
    __syncthreads();

    #pragma unroll
    for (int u = 0; u < TILE / 256; ++u) {
        int i = tileBase + u * 256 + tid;
        if (i < n) {
            int k   = kidx[i];
            int pos = atomicAdd(&cnts[k], 1);
            bins[k][pos] = i;
        }
    }
    __syncthreads();

    const int cnt = cnts[wid];
    if (cnt == 0) return;

    const unsigned xs_base =
        (unsigned)__cvta_generic_to_shared(&xstage[wid][0][0][0]);
    // buf stride = 4 slots * 128B = 512B; slot stride = 128B.

    // Prologue: stage chunk 0 into buffer 0; fetch its out-indices.
    int oq[4];
    #pragma unroll
    for (int d = 0; d < 4; ++d) {
        if (d < cnt) {
            int i = bins[wid][d];
            const float* src = x + (size_t)i * C_IN + lane;
            unsigned dst = xs_base + d * 128 + lane * 4;
            asm volatile("cp.async.ca.shared.global [%0], [%1], 4;"
                         :: "r"(dst), "l"(src));
            oq[d] = oidx[i];
        } else oq[d] = 0;
    }
    asm volatile("cp.async.commit_group;");

    for (int base = 0; base < cnt; base += 4) {
        const int buf = (base >> 2) & 1;

        // Stage NEXT chunk into the other buffer + fetch its out-indices.
        int on[4];
        #pragma unroll
        for (int d = 0; d < 4; ++d) {
            int pf = base + 4 + d;
            if (pf < cnt) {
                int i = bins[wid][pf];
                const float* src = x + (size_t)i * C_IN + lane;
                unsigned dst = xs_base + (buf ^ 1) * 512 + d * 128 + lane * 4;
                asm volatile("cp.async.ca.shared.global [%0], [%1], 4;"
                             :: "r"(dst), "l"(src));
                on[d] = oidx[i];
            } else on[d] = 0;
        }
        asm volatile("cp.async.commit_group;");

        // Current chunk's copies complete (<=1 pending group), visible warp-wide.
        asm volatile("cp.async.wait_group 1;");
        __syncwarp();

        #pragma unroll
        for (int d = 0; d < 4; ++d) {
            if (base + d < cnt) {
                const float4* xb = &xstage[wid][buf][d][0];
                unsigned long long acc0 = 0ull, acc1 = 0ull;
                #pragma unroll
                for (int t = 0; t < C_IN / 4; ++t) {
                    float4 v = xb[t];                         // broadcast LDS.128
                    unsigned long long v01 = pack2(v.x, v.y); // reg-pair, free
                    unsigned long long v23 = pack2(v.z, v.w);
                    FMA_F32X2(acc0, v01, wp0[2 * t]);
                    FMA_F32X2(acc1, v01, wp1[2 * t]);
                    FMA_F32X2(acc0, v23, wp0[2 * t + 1]);
                    FMA_F32X2(acc1, v23, wp1[2 * t + 1]);
                }
                float a0l, a0h, a1l, a1h;
                unpack2(acc0, a0l, a0h);
                unpack2(acc1, a1l, a1h);
                float a0 = a0l + a0h;       // channel 2*lane
                float a1 = a1l + a1h;       // channel 2*lane + 1

                float2* dst = (float2*)(out + (size_t)oq[d] * C_OUT) + lane;
                atomicAdd(dst, make_float2(a0, a1));   // RED.64
            }
        }

        #pragma unroll
        for (int d = 0; d < 4; ++d) oq[d] = on[d];
    }
}

// ---------------------------------------------------------------------------
// Pass B: per-channel sum / sum-of-squares, float4 + unroll-4 for MLP.
// ---------------------------------------------------------------------------
__global__ void stats_pass(const float4* __restrict__ out4, int n4)
{
    float4 s  = make_float4(0.f, 0.f, 0.f, 0.f);
    float4 s2 = make_float4(0.f, 0.f, 0.f, 0.f);
    const int start  = blockIdx.x * blockDim.x + threadIdx.x;
    const int stride = blockDim.x * gridDim.x;   // multiple of 16
    for (int i = start; i < n4; i += 4 * stride) {
        #pragma unroll
        for (int u = 0; u < 4; ++u) {
            int j = i + u * stride;
            if (j < n4) {
                float4 v = out4[j];
                s.x += v.x; s.y += v.y; s.z += v.z; s.w += v.w;
                s2.x = fmaf(v.x, v.x, s2.x);
                s2.y = fmaf(v.y, v.y, s2.y);
                s2.z = fmaf(v.z, v.z, s2.z);
                s2.w = fmaf(v.w, v.w, s2.w);
            }
        }
    }

    __shared__ float sh1[C_OUT], sh2[C_OUT];
    if (threadIdx.x < C_OUT) { sh1[threadIdx.x] = 0.f; sh2[threadIdx.x] = 0.f; }
    __syncthreads();
    const int cg = (start & 15) * 4;             // fixed channel group base
    atomicAdd(&sh1[cg + 0], s.x);  atomicAdd(&sh1[cg + 1], s.y);
    atomicAdd(&sh1[cg + 2], s.z);  atomicAdd(&sh1[cg + 3], s.w);
    atomicAdd(&sh2[cg + 0], s2.x); atomicAdd(&sh2[cg + 1], s2.y);
    atomicAdd(&sh2[cg + 2], s2.z); atomicAdd(&sh2[cg + 3], s2.w);
    __syncthreads();
    if (threadIdx.x < C_OUT) {
        atomicAdd(&g_sum[threadIdx.x],   sh1[threadIdx.x]);
        atomicAdd(&g_sumsq[threadIdx.x], sh2[threadIdx.x]);
    }
}

// ---------------------------------------------------------------------------
// Pass C: finalize BN affine (conv bias cancels algebraically).
// ---------------------------------------------------------------------------
__global__ void finalize_stats(const float* __restrict__ gamma,
                               const float* __restrict__ beta,
                               float inv_n)
{
    const int c = threadIdx.x;
    float mean = g_sum[c] * inv_n;
    float var  = g_sumsq[c] * inv_n - mean * mean;
    float a    = gamma[c] * rsqrtf(var + EPS);
    g_a[c] = a;
    g_b[c] = fmaf(-mean, a, beta[c]);
}

// ---------------------------------------------------------------------------
// Pass D: in-place normalize + ReLU, float4 + unroll-2.
// ---------------------------------------------------------------------------
__global__ void norm_relu(float4* __restrict__ out4, int n4)
{
    const int start  = blockIdx.x * blockDim.x + threadIdx.x;
    const int stride = blockDim.x * gridDim.x;   // multiple of 16
    const int cg = (start & 15) * 4;
    const float4 a = *(const float4*)&g_a[cg];
    const float4 b = *(const float4*)&g_b[cg];
    for (int i = start; i < n4; i += 2 * stride) {
        float4 v0 = out4[i];
        int j = i + stride;
        bool has1 = (j < n4);
        float4 v1 = has1 ? out4[j] : make_float4(0.f, 0.f, 0.f, 0.f);
        v0.x = fmaxf(fmaf(v0.x, a.x, b.x), 0.f);
        v0.y = fmaxf(fmaf(v0.y, a.y, b.y), 0.f);
        v0.z = fmaxf(fmaf(v0.z, a.z, b.z), 0.f);
        v0.w = fmaxf(fmaf(v0.w, a.w, b.w), 0.f);
        out4[i] = v0;
        if (has1) {
            v1.x = fmaxf(fmaf(v1.x, a.x, b.x), 0.f);
            v1.y = fmaxf(fmaf(v1.y, a.y, b.y), 0.f);
            v1.z = fmaxf(fmaf(v1.z, a.z, b.z), 0.f);
            v1.w = fmaxf(fmaf(v1.w, a.w, b.w), 0.f);
            out4[j] = v1;
        }
    }
}

// ---------------------------------------------------------------------------
// Launch. Inputs: x, W, bias, gamma, beta, k_idx, out_idx, num_out.
// ---------------------------------------------------------------------------
extern "C" void kernel_launch(void* const* d_in, const int* in_sizes, int n_in,
                              void* d_out, int out_size)
{
    const float* x     = (const float*)d_in[0];
    const float* W     = (const float*)d_in[1];
    const float* gamma = (const float*)d_in[3];
    const float* beta  = (const float*)d_in[4];
    const int*   kidx  = (const int*)d_in[5];
    const int*   oidx  = (const int*)d_in[6];

    const int n       = in_sizes[0] / C_IN;
    const int total   = out_size;               // num_out * 64
    const int num_out = total / C_OUT;
    const int n4      = total / 4;

    cudaMemsetAsync(d_out, 0, (size_t)total * sizeof(float), 0);

    const int tiles = (n + TILE - 1) / TILE;
    conv_scatter<<<tiles, 256>>>(x, W, kidx, oidx, (float*)d_out, n);
    stats_pass<<<1184, 256>>>((const float4*)d_out, n4);
    finalize_stats<<<1, C_OUT>>>(gamma, beta, 1.0f / (float)num_out);
    norm_relu<<<1184, 256>>>((float4*)d_out, n4);
}